// round 3
// baseline (speedup 1.0000x reference)
#include <cuda_runtime.h>
#include <cuda_bf16.h>
#include <cstdint>

// Problem constants
#define BATCH     32768
#define DIM       512
#define NUM_STEPS 100
#define NTOT      (BATCH * DIM)       // 2^24 elements

// Scratch (allowed: __device__ globals, no runtime allocation)
__device__ float g_buf0[NTOT];
__device__ float g_buf1[NTOT];
__device__ float g_A[DIM * DIM];      // Aeff = I + 0.01*W_top
__device__ float g_s[DIM];            // s[j] = sum_k W_bot[k][j]

// ---------------------------------------------------------------------------
// Threefry-2x32 (20 rounds) — verified against Random123 test vectors
// ---------------------------------------------------------------------------
#define TF_ROUND(r) { x0 += x1; x1 = __funnelshift_l(x1, x1, (r)); x1 ^= x0; }

__device__ __forceinline__ void tf2x32(uint32_t k0, uint32_t k1,
                                       uint32_t x0, uint32_t x1,
                                       uint32_t& o0, uint32_t& o1) {
    uint32_t k2 = k0 ^ k1 ^ 0x1BD11BDAu;
    x0 += k0; x1 += k1;
    TF_ROUND(13) TF_ROUND(15) TF_ROUND(26) TF_ROUND(6)
    x0 += k1; x1 += k2 + 1u;
    TF_ROUND(17) TF_ROUND(29) TF_ROUND(16) TF_ROUND(24)
    x0 += k2; x1 += k0 + 2u;
    TF_ROUND(13) TF_ROUND(15) TF_ROUND(26) TF_ROUND(6)
    x0 += k0; x1 += k1 + 3u;
    TF_ROUND(17) TF_ROUND(29) TF_ROUND(16) TF_ROUND(24)
    x0 += k1; x1 += k2 + 4u;
    TF_ROUND(13) TF_ROUND(15) TF_ROUND(26) TF_ROUND(6)
    x0 += k2; x1 += k0 + 5u;
    o0 = x0; o1 = x1;
}

// ---------------------------------------------------------------------------
// bits -> N(0,1), matching jax.random.normal(f32):
//   f = bitcast((bits>>9) | 0x3f800000) - 1
//   u = f*2 + nextafter(-1,0)
//   n = sqrt(2) * erfinv(u)   (XLA ErfInv32 / Giles polynomial)
// ---------------------------------------------------------------------------
__device__ __forceinline__ float jax_normal(uint32_t bits) {
    float f = __uint_as_float((bits >> 9) | 0x3F800000u) - 1.0f;
    const float lo = __uint_as_float(0xBF7FFFFFu);   // nextafter(-1, 0)
    float u = f * 2.0f + lo;
    float w = -log1pf(-u * u);
    float p;
    if (w < 5.0f) {
        w = w - 2.5f;
        p = 2.81022636e-08f;
        p = fmaf(p, w, 3.43273939e-07f);
        p = fmaf(p, w, -3.5233877e-06f);
        p = fmaf(p, w, -4.39150654e-06f);
        p = fmaf(p, w, 0.00021858087f);
        p = fmaf(p, w, -0.00125372503f);
        p = fmaf(p, w, -0.00417768164f);
        p = fmaf(p, w, 0.246640727f);
        p = fmaf(p, w, 1.50140941f);
    } else {
        w = sqrtf(w) - 3.0f;
        p = -0.000200214257f;
        p = fmaf(p, w, 0.000100950558f);
        p = fmaf(p, w, 0.00134934322f);
        p = fmaf(p, w, -0.00367342844f);
        p = fmaf(p, w, 0.00573950773f);
        p = fmaf(p, w, -0.0076224613f);
        p = fmaf(p, w, 0.00943887047f);
        p = fmaf(p, w, 1.00167406f);
        p = fmaf(p, w, 2.83297682f);
    }
    return 1.41421356237f * (p * u);
}

// ---------------------------------------------------------------------------
// Prep kernels
// ---------------------------------------------------------------------------
__global__ void prep_a_kernel(const float* __restrict__ W) {
    int i = blockIdx.x * blockDim.x + threadIdx.x;
    if (i < DIM * DIM) {
        int k = i >> 9, j = i & 511;
        g_A[i] = 0.01f * W[i] + (k == j ? 1.0f : 0.0f);
    }
}

__global__ void prep_s_kernel(const float* __restrict__ W) {
    int j = threadIdx.x;   // 512 threads, 1 block
    float s = 0.0f;
    #pragma unroll 8
    for (int k = 0; k < DIM; k++)
        s += W[(DIM + k) * DIM + j];
    g_s[j] = s;
}

// ---------------------------------------------------------------------------
// Fused step: dst = src @ Aeff + 0.01*(t*s + b) + sqrt(0.02)*noise_t
// Noise: JAX partitionable threefry — per element i: block (0, i), bits=w0^w1
// SIMT fp32 GEMM: BM=128, BN=128, BK=16, 256 threads, 8x8 per thread
// ---------------------------------------------------------------------------
__global__ void __launch_bounds__(256)
step_kernel(const float* __restrict__ src, float* __restrict__ dst,
            const float* __restrict__ bias, int t) {
    __shared__ float sA[16][128];   // transposed x tile (k-major)
    __shared__ float sB[16][128];   // Aeff tile

    const int tx = threadIdx.x, ty = threadIdx.y;      // 16 x 16
    const int tid = ty * 16 + tx;
    const int row0 = blockIdx.y * 128;
    const int col0 = blockIdx.x * 128;

    float acc[8][8];
    #pragma unroll
    for (int i = 0; i < 8; i++)
        #pragma unroll
        for (int j = 0; j < 8; j++) acc[i][j] = 0.0f;

    for (int k0 = 0; k0 < DIM; k0 += 16) {
        // Load A (x) tile: 128 rows x 16 cols, 2 float4 per thread, transposed
        #pragma unroll
        for (int l = 0; l < 2; l++) {
            int lin = tid + l * 256;          // 0..511
            int r = lin >> 2, c4 = lin & 3;   // 128 rows x 4 float4
            float4 v = *(const float4*)(src + (row0 + r) * DIM + k0 + c4 * 4);
            sA[c4 * 4 + 0][r] = v.x;
            sA[c4 * 4 + 1][r] = v.y;
            sA[c4 * 4 + 2][r] = v.z;
            sA[c4 * 4 + 3][r] = v.w;
        }
        // Load B (Aeff) tile: 16 rows x 128 cols, 2 float4 per thread
        #pragma unroll
        for (int l = 0; l < 2; l++) {
            int lin = tid + l * 256;          // 0..511
            int r = lin >> 5, c4 = lin & 31;  // 16 rows x 32 float4
            float4 v = *(const float4*)(g_A + (k0 + r) * DIM + col0 + c4 * 4);
            *(float4*)&sB[r][c4 * 4] = v;
        }
        __syncthreads();

        #pragma unroll
        for (int kk = 0; kk < 16; kk++) {
            float ra[8], rb[8];
            #pragma unroll
            for (int i = 0; i < 8; i += 4)
                *(float4*)&ra[i] = *(const float4*)&sA[kk][ty * 8 + i];
            #pragma unroll
            for (int j = 0; j < 8; j += 4)
                *(float4*)&rb[j] = *(const float4*)&sB[kk][tx * 8 + j];
            #pragma unroll
            for (int i = 0; i < 8; i++)
                #pragma unroll
                for (int j = 0; j < 8; j++)
                    acc[i][j] = fmaf(ra[i], rb[j], acc[i][j]);
        }
        __syncthreads();
    }

    // Epilogue. Per-step key = fold_in(key(42), t) = threefry((0,42), (0,t)).
    uint32_t fk1, fk2;
    tf2x32(0u, 42u, 0u, (uint32_t)t, fk1, fk2);
    const float tf = (float)t;
    const float S2B = sqrtf(2.0f * 0.01f);

    // Hoist column-dependent affine term
    float cb[8];
    #pragma unroll
    for (int j = 0; j < 8; j++) {
        int c = col0 + tx * 8 + j;
        cb[j] = 0.01f * (tf * g_s[c] + bias[c]);
    }

    #pragma unroll 1   // keep code size small (one threefry block per element)
    for (int i = 0; i < 8; i++) {
        int r = row0 + ty * 8 + i;
        uint32_t base = (uint32_t)(r * DIM + col0 + tx * 8);
        float outv[8];
        #pragma unroll
        for (int j = 0; j < 8; j++) {
            uint32_t w0, w1;
            tf2x32(fk1, fk2, 0u, base + (uint32_t)j, w0, w1);
            float nz = jax_normal(w0 ^ w1);
            outv[j] = acc[i][j] + cb[j] + S2B * nz;
        }
        *(float4*)(dst + r * DIM + col0 + tx * 8) =
            make_float4(outv[0], outv[1], outv[2], outv[3]);
        *(float4*)(dst + r * DIM + col0 + tx * 8 + 4) =
            make_float4(outv[4], outv[5], outv[6], outv[7]);
    }
}

// ---------------------------------------------------------------------------
extern "C" void kernel_launch(void* const* d_in, const int* in_sizes, int n_in,
                              void* d_out, int out_size) {
    const float* x0 = (const float*)d_in[0];   // (32768, 512)
    const float* W  = (const float*)d_in[1];   // (1024, 512)
    const float* b  = (const float*)d_in[2];   // (512,)
    float* out = (float*)d_out;

    float *buf0, *buf1;
    cudaGetSymbolAddress((void**)&buf0, g_buf0);
    cudaGetSymbolAddress((void**)&buf1, g_buf1);

    prep_a_kernel<<<(DIM * DIM + 255) / 256, 256>>>(W);
    prep_s_kernel<<<1, DIM>>>(W);

    dim3 block(16, 16);
    dim3 grid(DIM / 128, BATCH / 128);   // (4, 256)

    for (int t = 0; t < NUM_STEPS; t++) {
        const float* src = (t == 0) ? x0 : ((t & 1) ? buf1 : buf0);
        float* dst = (t == NUM_STEPS - 1) ? out : (((t + 1) & 1) ? buf1 : buf0);
        step_kernel<<<grid, block>>>(src, dst, b, t);
    }
}

// round 6
// speedup vs baseline: 1.4875x; 1.4875x over previous
#include <cuda_runtime.h>
#include <cuda_fp16.h>
#include <cstdint>

// Problem constants
#define BATCH     32768
#define DIM       512
#define NUM_STEPS 100
#define NTOT      (BATCH * DIM)       // 2^24 elements

// ---------------------------------------------------------------------------
// Device scratch (no runtime allocation allowed)
// ---------------------------------------------------------------------------
__device__ float  g_buf0[NTOT];
__device__ float  g_buf1[NTOT];
__device__ __half g_hi0[NTOT];
__device__ __half g_lo0[NTOT];
__device__ __half g_hi1[NTOT];
__device__ __half g_lo1[NTOT];
__device__ __half g_Bhi[DIM * DIM];   // W_top^T [n][k] hi (fp16)
__device__ __half g_Blo[DIM * DIM];   // W_top^T [n][k] lo (fp16)
__device__ float  g_s[DIM];           // s[j] = sum_k W_bot[k][j]

// ---------------------------------------------------------------------------
// PTX helpers — sm_80-baseline features only (no 'a'-gated instructions)
// ---------------------------------------------------------------------------
__device__ __forceinline__ uint32_t smem_u32(const void* p) {
    uint32_t a;
    asm("{ .reg .u64 t; cvta.to.shared.u64 t, %1; cvt.u32.u64 %0, t; }"
        : "=r"(a) : "l"(p));
    return a;
}

__device__ __forceinline__ void cpa16(uint32_t s, const void* g) {
    asm volatile("cp.async.cg.shared.global [%0], [%1], 16;"
                 :: "r"(s), "l"(g) : "memory");
}

__device__ __forceinline__ void cp_commit() {
    asm volatile("cp.async.commit_group;" ::: "memory");
}

template <int N>
__device__ __forceinline__ void cp_wait() {
    asm volatile("cp.async.wait_group %0;" :: "n"(N) : "memory");
}

__device__ __forceinline__ void ldsm4(uint32_t* r, uint32_t addr) {
    asm volatile("ldmatrix.sync.aligned.m8n8.x4.shared.b16 {%0,%1,%2,%3}, [%4];"
                 : "=r"(r[0]), "=r"(r[1]), "=r"(r[2]), "=r"(r[3]) : "r"(addr));
}

__device__ __forceinline__ void mma16816(float* d, const uint32_t* a,
                                         const uint32_t* b) {
    asm volatile(
        "mma.sync.aligned.m16n8k16.row.col.f32.f16.f16.f32 "
        "{%0,%1,%2,%3}, {%4,%5,%6,%7}, {%8,%9}, {%0,%1,%2,%3};"
        : "+f"(d[0]), "+f"(d[1]), "+f"(d[2]), "+f"(d[3])
        : "r"(a[0]), "r"(a[1]), "r"(a[2]), "r"(a[3]), "r"(b[0]), "r"(b[1]));
}

// ---------------------------------------------------------------------------
// Threefry-2x32 (20 rounds) + JAX normal — bit-exact (verified round 3)
// ---------------------------------------------------------------------------
#define TF_ROUND(r) { x0 += x1; x1 = __funnelshift_l(x1, x1, (r)); x1 ^= x0; }

__device__ __forceinline__ void tf2x32(uint32_t k0, uint32_t k1,
                                       uint32_t x0, uint32_t x1,
                                       uint32_t& o0, uint32_t& o1) {
    uint32_t k2 = k0 ^ k1 ^ 0x1BD11BDAu;
    x0 += k0; x1 += k1;
    TF_ROUND(13) TF_ROUND(15) TF_ROUND(26) TF_ROUND(6)
    x0 += k1; x1 += k2 + 1u;
    TF_ROUND(17) TF_ROUND(29) TF_ROUND(16) TF_ROUND(24)
    x0 += k2; x1 += k0 + 2u;
    TF_ROUND(13) TF_ROUND(15) TF_ROUND(26) TF_ROUND(6)
    x0 += k0; x1 += k1 + 3u;
    TF_ROUND(17) TF_ROUND(29) TF_ROUND(16) TF_ROUND(24)
    x0 += k1; x1 += k2 + 4u;
    TF_ROUND(13) TF_ROUND(15) TF_ROUND(26) TF_ROUND(6)
    x0 += k2; x1 += k0 + 5u;
    o0 = x0; o1 = x1;
}

__device__ __forceinline__ float jax_normal(uint32_t bits) {
    float f = __uint_as_float((bits >> 9) | 0x3F800000u) - 1.0f;
    const float lo = __uint_as_float(0xBF7FFFFFu);   // nextafter(-1, 0)
    float u = f * 2.0f + lo;
    float w = -log1pf(-u * u);
    float p;
    if (w < 5.0f) {
        w = w - 2.5f;
        p = 2.81022636e-08f;
        p = fmaf(p, w, 3.43273939e-07f);
        p = fmaf(p, w, -3.5233877e-06f);
        p = fmaf(p, w, -4.39150654e-06f);
        p = fmaf(p, w, 0.00021858087f);
        p = fmaf(p, w, -0.00125372503f);
        p = fmaf(p, w, -0.00417768164f);
        p = fmaf(p, w, 0.246640727f);
        p = fmaf(p, w, 1.50140941f);
    } else {
        w = sqrtf(w) - 3.0f;
        p = -0.000200214257f;
        p = fmaf(p, w, 0.000100950558f);
        p = fmaf(p, w, 0.00134934322f);
        p = fmaf(p, w, -0.00367342844f);
        p = fmaf(p, w, 0.00573950773f);
        p = fmaf(p, w, -0.0076224613f);
        p = fmaf(p, w, 0.00943887047f);
        p = fmaf(p, w, 1.00167406f);
        p = fmaf(p, w, 2.83297682f);
    }
    return 1.41421356237f * (p * u);
}

// ---------------------------------------------------------------------------
// Prep kernels
// ---------------------------------------------------------------------------
__global__ void prep_b_kernel(const float* __restrict__ W) {
    int i = blockIdx.x * blockDim.x + threadIdx.x;   // i = n*512 + k
    if (i < DIM * DIM) {
        int n = i >> 9, k = i & 511;
        float v = W[k * DIM + n];                    // W_top[k][n]
        __half h = __float2half_rn(v);
        g_Bhi[i] = h;
        g_Blo[i] = __float2half_rn(v - __half2float(h));
    }
}

__global__ void prep_s_kernel(const float* __restrict__ W) {
    int j = threadIdx.x;   // 512 threads, 1 block
    float s = 0.0f;
    #pragma unroll 8
    for (int k = 0; k < DIM; k++)
        s += W[(DIM + k) * DIM + j];
    g_s[j] = s;
}

__global__ void prep_x_kernel(const float* __restrict__ x0) {
    int i = blockIdx.x * blockDim.x + threadIdx.x;
    float v = x0[i];
    __half h = __float2half_rn(v);
    g_hi0[i] = h;
    g_lo0[i] = __float2half_rn(v - __half2float(h));
}

// ---------------------------------------------------------------------------
// Fused step kernel (HMMA mma.sync path):
//   score = x_hi@W_hi + x_lo@W_hi + x_hi@W_lo  (fp16 in, f32 acc)
//   x_next = x + 0.01*score + 0.01*(t*s + b) + sqrt(0.02)*noise
// CTA tile 128x128, 8 warps (4M x 2N), BK=32, cp.async double buffer.
// ---------------------------------------------------------------------------
#define BK      32
#define ROWB    80                      // 32 halves (64B) + 16B pad
#define TILE_B  (128 * ROWB)            // 10240 bytes per tile
#define STAGE_B (4 * TILE_B)            // Ahi, Alo, Bhi, Blo
#define SMEM_TOTAL (2 * STAGE_B + 512)  // + cbias[128]

__global__ void __launch_bounds__(256, 2)
step_kernel(const float* __restrict__ xold,
            float* __restrict__ xnew,
            const __half* __restrict__ Ahi,
            const __half* __restrict__ Alo,
            __half* __restrict__ hi_out,
            __half* __restrict__ lo_out,
            const float* __restrict__ bias,
            int t) {
    extern __shared__ char smem[];
    const uint32_t base = smem_u32(smem);
    float* cbias = (float*)(smem + 2 * STAGE_B);   // 128 floats

    const int tid = threadIdx.x;
    const int wid = tid >> 5, lane = tid & 31;
    const int warp_m = wid & 3, warp_n = wid >> 2;
    const int m0 = blockIdx.y * 128, n0 = blockIdx.x * 128;
    const float tf = (float)t;

    // Column bias table for this CTA's 128 columns
    if (tid < 128) {
        int c = n0 + tid;
        cbias[tid] = 0.01f * (tf * g_s[c] + bias[c]);
    }

    float acc[2][8][4];
    #pragma unroll
    for (int mt = 0; mt < 2; mt++)
        #pragma unroll
        for (int nt = 0; nt < 8; nt++)
            #pragma unroll
            for (int q = 0; q < 4; q++) acc[mt][nt][q] = 0.0f;

    // ---- tile load (cp.async): stage st, k-chunk kc ----
    const int ldRow = tid >> 2, ldC = tid & 3;          // 2 chunks per thread
    auto issue_load = [&](int st, int kc) {
        const uint32_t sb = base + st * STAGE_B;
        const int koff = kc * BK;
        #pragma unroll
        for (int l = 0; l < 2; l++) {
            int row = ldRow + l * 64;
            uint32_t so = row * ROWB + ldC * 16;
            size_t gA = (size_t)(m0 + row) * DIM + koff + ldC * 8;
            size_t gB = (size_t)(n0 + row) * DIM + koff + ldC * 8;
            cpa16(sb + 0 * TILE_B + so, Ahi + gA);
            cpa16(sb + 1 * TILE_B + so, Alo + gA);
            cpa16(sb + 2 * TILE_B + so, g_Bhi + gB);
            cpa16(sb + 3 * TILE_B + so, g_Blo + gB);
        }
        cp_commit();
    };

    // ldmatrix per-thread base addresses (within a stage)
    const uint32_t aRow = (warp_m * 32 + (lane & 15)) * ROWB;
    const uint32_t aChunk = (uint32_t)(lane >> 4) * 16;          // 0 or 16 B
    const uint32_t bRow = (warp_n * 64 + (lane & 7) + ((lane >> 4) << 3)) * ROWB;
    const uint32_t bChunk = (uint32_t)((lane >> 3) & 1) * 16;    // 0 or 16 B

    issue_load(0, 0);

    #pragma unroll 1
    for (int kc = 0; kc < DIM / BK; kc++) {
        const int buf = kc & 1;
        if (kc + 1 < DIM / BK) { issue_load(buf ^ 1, kc + 1); cp_wait<1>(); }
        else                   { cp_wait<0>(); }
        __syncthreads();

        const uint32_t sb = base + buf * STAGE_B;
        #pragma unroll
        for (int s = 0; s < 2; s++) {
            const uint32_t kb = (uint32_t)s * 32;   // 16 halves = 32 B
            uint32_t ahi[2][4], alo[2][4];
            #pragma unroll
            for (int mt = 0; mt < 2; mt++) {
                uint32_t ao = aRow + mt * 16 * ROWB + kb + aChunk;
                ldsm4(ahi[mt], sb + 0 * TILE_B + ao);
                ldsm4(alo[mt], sb + 1 * TILE_B + ao);
            }
            #pragma unroll
            for (int p = 0; p < 4; p++) {
                uint32_t bo = bRow + p * 16 * ROWB + kb + bChunk;
                uint32_t bh[4], bl[4];
                ldsm4(bh, sb + 2 * TILE_B + bo);
                ldsm4(bl, sb + 3 * TILE_B + bo);
                #pragma unroll
                for (int mt = 0; mt < 2; mt++) {
                    mma16816(acc[mt][2 * p],     ahi[mt], bh);
                    mma16816(acc[mt][2 * p],     alo[mt], bh);
                    mma16816(acc[mt][2 * p],     ahi[mt], bl);
                    mma16816(acc[mt][2 * p + 1], ahi[mt], bh + 2);
                    mma16816(acc[mt][2 * p + 1], alo[mt], bh + 2);
                    mma16816(acc[mt][2 * p + 1], ahi[mt], bl + 2);
                }
            }
        }
        __syncthreads();
    }

    // ---- Epilogue: threefry noise + state update, from register accum ----
    uint32_t fk1, fk2;
    tf2x32(0u, 42u, 0u, (uint32_t)t, fk1, fk2);
    const float S2B = sqrtf(2.0f * 0.01f);

    #pragma unroll
    for (int mt = 0; mt < 2; mt++) {
        #pragma unroll
        for (int h = 0; h < 2; h++) {
            const int r = m0 + warp_m * 32 + mt * 16 + (lane >> 2) + h * 8;
            const size_t rowoff = (size_t)r * DIM;
            #pragma unroll 1
            for (int nt = 0; nt < 8; nt++) {
                const int cl = warp_n * 64 + nt * 8 + (lane & 3) * 2;
                const size_t off = rowoff + (n0 + cl);
                const float2 xo = *(const float2*)(xold + off);
                uint32_t w0, w1, v0, v1;
                tf2x32(fk1, fk2, 0u, (uint32_t)off, w0, w1);
                tf2x32(fk1, fk2, 0u, (uint32_t)off + 1u, v0, v1);
                float xn0 = xo.x + 0.01f * acc[mt][nt][h * 2 + 0] + cbias[cl]
                            + S2B * jax_normal(w0 ^ w1);
                float xn1 = xo.y + 0.01f * acc[mt][nt][h * 2 + 1] + cbias[cl + 1]
                            + S2B * jax_normal(v0 ^ v1);
                *(float2*)(xnew + off) = make_float2(xn0, xn1);
                __half h0 = __float2half_rn(xn0);
                __half h1 = __float2half_rn(xn1);
                __half l0 = __float2half_rn(xn0 - __half2float(h0));
                __half l1 = __float2half_rn(xn1 - __half2float(h1));
                *(uint32_t*)(hi_out + off) =
                    (uint32_t)__half_as_ushort(h0) |
                    ((uint32_t)__half_as_ushort(h1) << 16);
                *(uint32_t*)(lo_out + off) =
                    (uint32_t)__half_as_ushort(l0) |
                    ((uint32_t)__half_as_ushort(l1) << 16);
            }
        }
    }
}

// ---------------------------------------------------------------------------
// Host side
// ---------------------------------------------------------------------------
extern "C" void kernel_launch(void* const* d_in, const int* in_sizes, int n_in,
                              void* d_out, int out_size) {
    const float* x0 = (const float*)d_in[0];   // (32768, 512)
    const float* W  = (const float*)d_in[1];   // (1024, 512)
    const float* b  = (const float*)d_in[2];   // (512,)
    float* out = (float*)d_out;

    void *buf0, *buf1, *hi0, *lo0, *hi1, *lo1;
    cudaGetSymbolAddress(&buf0, g_buf0);
    cudaGetSymbolAddress(&buf1, g_buf1);
    cudaGetSymbolAddress(&hi0, g_hi0);
    cudaGetSymbolAddress(&lo0, g_lo0);
    cudaGetSymbolAddress(&hi1, g_hi1);
    cudaGetSymbolAddress(&lo1, g_lo1);

    cudaFuncSetAttribute(step_kernel,
                         cudaFuncAttributeMaxDynamicSharedMemorySize, SMEM_TOTAL);

    prep_b_kernel<<<(DIM * DIM + 255) / 256, 256>>>(W);
    prep_s_kernel<<<1, DIM>>>(W);
    prep_x_kernel<<<NTOT / 256, 256>>>(x0);

    dim3 grid(DIM / 128, BATCH / 128);   // (4, 256)
    for (int t = 0; t < NUM_STEPS; t++) {
        bool even = (t & 1) == 0;
        const float* xold = (t == 0) ? x0
                            : (even ? (const float*)buf0 : (const float*)buf1);
        float* xnew = (t == NUM_STEPS - 1) ? out
                      : (even ? (float*)buf1 : (float*)buf0);
        const __half* Ahi = even ? (const __half*)hi0 : (const __half*)hi1;
        const __half* Alo = even ? (const __half*)lo0 : (const __half*)lo1;
        __half* ho = even ? (__half*)hi1 : (__half*)hi0;
        __half* lo = even ? (__half*)lo1 : (__half*)lo0;
        step_kernel<<<grid, 256, SMEM_TOTAL>>>(xold, xnew, Ahi, Alo,
                                               ho, lo, b, t);
    }
}

// round 7
// speedup vs baseline: 1.6648x; 1.1192x over previous
#include <cuda_runtime.h>
#include <cuda.h>
#include <cuda_fp16.h>
#include <cstdint>

// Problem constants
#define BATCH     32768
#define DIM       512
#define NUM_STEPS 100
#define NTOT      (BATCH * DIM)       // 2^24 elements

// ---------------------------------------------------------------------------
// Device scratch (no runtime allocation allowed)
// ---------------------------------------------------------------------------
__device__ __half g_hi0[NTOT];
__device__ __half g_lo0[NTOT];
__device__ __half g_hi1[NTOT];
__device__ __half g_lo1[NTOT];
__device__ __half g_Bhi[DIM * DIM];   // W_top^T [n][k] (fp16)
__device__ float  g_s[DIM];           // s[j] = sum_k W_bot[k][j]

// ---------------------------------------------------------------------------
// PTX helpers (sm_90-baseline: TMA bulk + mbarrier; NO 'a'-gated instrs)
// ---------------------------------------------------------------------------
__device__ __forceinline__ uint32_t smem_u32(const void* p) {
    uint32_t a;
    asm("{ .reg .u64 t; cvta.to.shared.u64 t, %1; cvt.u32.u64 %0, t; }"
        : "=r"(a) : "l"(p));
    return a;
}

#define MBARRIER_INIT(addr, cnt) \
    asm volatile("mbarrier.init.shared.b64 [%0], %1;" \
                 :: "r"((uint32_t)(addr)), "r"((uint32_t)(cnt)) : "memory")

#define MBARRIER_EXPECT_TX(addr, bytes) \
    asm volatile("mbarrier.arrive.expect_tx.shared.b64 _, [%0], %1;" \
                 :: "r"((uint32_t)(addr)), "r"((uint32_t)(bytes)) : "memory")

#define MBARRIER_ARRIVE(addr) \
    asm volatile("mbarrier.arrive.shared.b64 _, [%0];" \
                 :: "r"((uint32_t)(addr)) : "memory")

#define MBARRIER_WAIT_PARITY(addr, parity) do { \
    uint32_t _m = (uint32_t)(addr); \
    uint32_t _p = (uint32_t)(parity); \
    uint32_t _d; \
    asm volatile("{\n\t.reg .pred p;\n\t" \
        "mbarrier.try_wait.parity.acquire.cta.shared::cta.b64 p, [%1], %2;\n\t" \
        "selp.b32 %0, 1, 0, p;\n\t}" : "=r"(_d) : "r"(_m), "r"(_p) : "memory"); \
    if (!_d) { \
        asm volatile("{\n\t.reg .pred P1;\n\t" \
            "WL_%=:\n\t" \
            "mbarrier.try_wait.parity.acquire.cta.shared::cta.b64 P1, [%0], %1, 0x989680;\n\t" \
            "@P1 bra.uni WD_%=;\n\t" \
            "bra.uni WL_%=;\n\t" \
            "WD_%=:\n\t}" :: "r"(_m), "r"(_p) : "memory"); \
    } \
} while (0)

__device__ __forceinline__ void tma_load_2d(uint32_t smem_addr, const void* map,
                                            int cx, int cy, uint32_t mbar) {
    asm volatile(
        "cp.async.bulk.tensor.2d.shared::cta.global.tile.mbarrier::complete_tx::bytes "
        "[%0], [%1, {%2, %3}], [%4];"
        :: "r"(smem_addr), "l"(map), "r"(cx), "r"(cy), "r"(mbar) : "memory");
}

__device__ __forceinline__ void ldsm4(uint32_t* r, uint32_t addr) {
    asm volatile("ldmatrix.sync.aligned.m8n8.x4.shared.b16 {%0,%1,%2,%3}, [%4];"
                 : "=r"(r[0]), "=r"(r[1]), "=r"(r[2]), "=r"(r[3]) : "r"(addr));
}

__device__ __forceinline__ void mma16816(float* d, const uint32_t* a,
                                         const uint32_t* b) {
    asm volatile(
        "mma.sync.aligned.m16n8k16.row.col.f32.f16.f16.f32 "
        "{%0,%1,%2,%3}, {%4,%5,%6,%7}, {%8,%9}, {%0,%1,%2,%3};"
        : "+f"(d[0]), "+f"(d[1]), "+f"(d[2]), "+f"(d[3])
        : "r"(a[0]), "r"(a[1]), "r"(a[2]), "r"(a[3]), "r"(b[0]), "r"(b[1]));
}

// ---------------------------------------------------------------------------
// Threefry-2x32 (20 rounds) + JAX normal — bit-exact (verified round 3/6)
// ---------------------------------------------------------------------------
#define TF_ROUND(r) { x0 += x1; x1 = __funnelshift_l(x1, x1, (r)); x1 ^= x0; }

__device__ __forceinline__ void tf2x32(uint32_t k0, uint32_t k1,
                                       uint32_t x0, uint32_t x1,
                                       uint32_t& o0, uint32_t& o1) {
    uint32_t k2 = k0 ^ k1 ^ 0x1BD11BDAu;
    x0 += k0; x1 += k1;
    TF_ROUND(13) TF_ROUND(15) TF_ROUND(26) TF_ROUND(6)
    x0 += k1; x1 += k2 + 1u;
    TF_ROUND(17) TF_ROUND(29) TF_ROUND(16) TF_ROUND(24)
    x0 += k2; x1 += k0 + 2u;
    TF_ROUND(13) TF_ROUND(15) TF_ROUND(26) TF_ROUND(6)
    x0 += k0; x1 += k1 + 3u;
    TF_ROUND(17) TF_ROUND(29) TF_ROUND(16) TF_ROUND(24)
    x0 += k1; x1 += k2 + 4u;
    TF_ROUND(13) TF_ROUND(15) TF_ROUND(26) TF_ROUND(6)
    x0 += k2; x1 += k0 + 5u;
    o0 = x0; o1 = x1;
}

__device__ __forceinline__ float jax_normal(uint32_t bits) {
    float f = __uint_as_float((bits >> 9) | 0x3F800000u) - 1.0f;
    const float lo = __uint_as_float(0xBF7FFFFFu);   // nextafter(-1, 0)
    float u = f * 2.0f + lo;
    float w = -log1pf(-u * u);
    float p;
    if (w < 5.0f) {
        w = w - 2.5f;
        p = 2.81022636e-08f;
        p = fmaf(p, w, 3.43273939e-07f);
        p = fmaf(p, w, -3.5233877e-06f);
        p = fmaf(p, w, -4.39150654e-06f);
        p = fmaf(p, w, 0.00021858087f);
        p = fmaf(p, w, -0.00125372503f);
        p = fmaf(p, w, -0.00417768164f);
        p = fmaf(p, w, 0.246640727f);
        p = fmaf(p, w, 1.50140941f);
    } else {
        w = sqrtf(w) - 3.0f;
        p = -0.000200214257f;
        p = fmaf(p, w, 0.000100950558f);
        p = fmaf(p, w, 0.00134934322f);
        p = fmaf(p, w, -0.00367342844f);
        p = fmaf(p, w, 0.00573950773f);
        p = fmaf(p, w, -0.0076224613f);
        p = fmaf(p, w, 0.00943887047f);
        p = fmaf(p, w, 1.00167406f);
        p = fmaf(p, w, 2.83297682f);
    }
    return 1.41421356237f * (p * u);
}

// ---------------------------------------------------------------------------
// Prep kernels
// ---------------------------------------------------------------------------
__global__ void prep_b_kernel(const float* __restrict__ W) {
    int i = blockIdx.x * blockDim.x + threadIdx.x;   // i = n*512 + k
    if (i < DIM * DIM) {
        int n = i >> 9, k = i & 511;
        g_Bhi[i] = __float2half_rn(W[k * DIM + n]);  // W_top[k][n]
    }
}

__global__ void prep_s_kernel(const float* __restrict__ W) {
    int j = threadIdx.x;   // 512 threads, 1 block
    float s = 0.0f;
    #pragma unroll 8
    for (int k = 0; k < DIM; k++)
        s += W[(DIM + k) * DIM + j];
    g_s[j] = s;
}

__global__ void prep_x_kernel(const float* __restrict__ x0) {
    int i = blockIdx.x * blockDim.x + threadIdx.x;
    float v = x0[i];
    __half h = __float2half_rn(v);
    g_hi0[i] = h;
    g_lo0[i] = __float2half_rn(v - __half2float(h));
}

// ---------------------------------------------------------------------------
// Fused step kernel (TMA + HMMA):
//   score = (x_hi + x_lo) @ W_hi  (fp16 in, f32 acc)
//   x_next = (hi+lo) + 0.01*score + 0.01*(t*s + b) + sqrt(0.02)*noise
// CTA tile 128x128, 8 warps (4M x 2N), BK=64, TMA SW128 double buffer.
// ---------------------------------------------------------------------------
#define NCH       8                    // 512 / 64
#define TILE_SZ   16384                // 128 rows x 128 B
#define STAGE_SZ  (3 * TILE_SZ)        // Ahi, Alo, Bhi
#define BAR_OFF   (2 * STAGE_SZ)       // 98304
#define CBIAS_OFF (BAR_OFF + 64)
#define SMEM_REQ  (CBIAS_OFF + 512 + 1024)   // + align slack

__global__ void __launch_bounds__(256, 2)
step_kernel(const __grid_constant__ CUtensorMap mAhi,
            const __grid_constant__ CUtensorMap mAlo,
            const __grid_constant__ CUtensorMap mBhi,
            const __half* __restrict__ hi_in,
            const __half* __restrict__ lo_in,
            __half* __restrict__ hi_out,
            __half* __restrict__ lo_out,
            float* __restrict__ fout,          // non-null only on last step
            const float* __restrict__ bias,
            int t) {
    extern __shared__ char smem[];
    const uint32_t sbRaw = smem_u32(smem);
    const uint32_t base  = (sbRaw + 1023u) & ~1023u;
    char* smemA = smem + (base - sbRaw);

    const uint32_t FULL0 = base + BAR_OFF,      FULL1 = base + BAR_OFF + 8;
    const uint32_t EMPT0 = base + BAR_OFF + 16, EMPT1 = base + BAR_OFF + 24;
    float* cbias = (float*)(smemA + CBIAS_OFF);     // 128 floats

    const int tid = threadIdx.x;
    const int wid = tid >> 5, lane = tid & 31;
    const int warp_m = wid & 3, warp_n = wid >> 2;
    const int m0 = blockIdx.y * 128, n0 = blockIdx.x * 128;
    const float tf = (float)t;

    if (tid < 128) {
        int c = n0 + tid;
        cbias[tid] = 0.01f * (tf * g_s[c] + bias[c]);
    }
    if (tid == 0) {
        MBARRIER_INIT(FULL0, 1);
        MBARRIER_INIT(FULL1, 1);
        MBARRIER_INIT(EMPT0, 256);
        MBARRIER_INIT(EMPT1, 256);
    }
    __syncthreads();

    float acc[2][8][4];
    #pragma unroll
    for (int mt = 0; mt < 2; mt++)
        #pragma unroll
        for (int nt = 0; nt < 8; nt++)
            #pragma unroll
            for (int q = 0; q < 4; q++) acc[mt][nt][q] = 0.0f;

    // Per-thread ldmatrix addressing (SW128: XOR sub-offset with (row&7)*16)
    const uint32_t xorS   = (uint32_t)(lane & 7) << 4;
    const uint32_t aRowOff = (uint32_t)(warp_m * 32 + (lane & 15)) * 128u;
    const uint32_t aSub    = (uint32_t)(lane >> 4) << 4;
    const uint32_t bRowOff = (uint32_t)(warp_n * 64 + (lane & 7) +
                                        ((lane >> 4) << 3)) * 128u;
    const uint32_t bSub    = (uint32_t)((lane >> 3) & 1) << 4;

    const uint32_t stg0 = base, stg1 = base + STAGE_SZ;

    // Prologue: chunk 0 into stage 0
    if (tid == 0) {
        MBARRIER_EXPECT_TX(FULL0, STAGE_SZ);
        tma_load_2d(stg0,               &mAhi, 0, m0, FULL0);
        tma_load_2d(stg0 + TILE_SZ,     &mAlo, 0, m0, FULL0);
        tma_load_2d(stg0 + 2 * TILE_SZ, &mBhi, 0, n0, FULL0);
    }

    #pragma unroll 1
    for (int c = 0; c < NCH; c++) {
        const int sbi = c & 1;
        const uint32_t sb = sbi ? stg1 : stg0;
        const uint32_t FULLC = sbi ? FULL1 : FULL0;
        MBARRIER_WAIT_PARITY(FULLC, (c >> 1) & 1);

        if (tid == 0 && c + 1 < NCH) {
            const int s2 = (c + 1) & 1, k2 = (c + 1) >> 1;
            const uint32_t EMPTN = s2 ? EMPT1 : EMPT0;
            const uint32_t FULLN = s2 ? FULL1 : FULL0;
            const uint32_t sn = s2 ? stg1 : stg0;
            if (k2 > 0) MBARRIER_WAIT_PARITY(EMPTN, (k2 - 1) & 1);
            MBARRIER_EXPECT_TX(FULLN, STAGE_SZ);
            const int k0 = (c + 1) * 64;
            tma_load_2d(sn,               &mAhi, k0, m0, FULLN);
            tma_load_2d(sn + TILE_SZ,     &mAlo, k0, m0, FULLN);
            tma_load_2d(sn + 2 * TILE_SZ, &mBhi, k0, n0, FULLN);
        }

        #pragma unroll
        for (int s = 0; s < 4; s++) {
            const uint32_t ka = ((uint32_t)(s * 32) + aSub) ^ xorS;
            const uint32_t kb = ((uint32_t)(s * 32) + bSub) ^ xorS;
            uint32_t ahi[2][4], alo[2][4];
            #pragma unroll
            for (int mt = 0; mt < 2; mt++) {
                const uint32_t ao = sb + aRowOff + (uint32_t)(mt * 16 * 128) + ka;
                ldsm4(ahi[mt], ao);
                ldsm4(alo[mt], ao + TILE_SZ);
            }
            #pragma unroll
            for (int p = 0; p < 4; p++) {
                uint32_t bh[4];
                ldsm4(bh, sb + 2 * TILE_SZ + bRowOff +
                          (uint32_t)(p * 16 * 128) + kb);
                #pragma unroll
                for (int mt = 0; mt < 2; mt++) {
                    mma16816(acc[mt][2 * p],     ahi[mt], bh);
                    mma16816(acc[mt][2 * p],     alo[mt], bh);
                    mma16816(acc[mt][2 * p + 1], ahi[mt], bh + 2);
                    mma16816(acc[mt][2 * p + 1], alo[mt], bh + 2);
                }
            }
        }
        MBARRIER_ARRIVE(sbi ? EMPT1 : EMPT0);
    }

    // ---- Epilogue: threefry noise + state update from register accum ----
    uint32_t fk1, fk2;
    tf2x32(0u, 42u, 0u, (uint32_t)t, fk1, fk2);
    const float S2B = sqrtf(2.0f * 0.01f);

    #pragma unroll
    for (int mt = 0; mt < 2; mt++) {
        #pragma unroll
        for (int h = 0; h < 2; h++) {
            const int r = m0 + warp_m * 32 + mt * 16 + (lane >> 2) + h * 8;
            const size_t rowoff = (size_t)r * DIM;
            #pragma unroll 1
            for (int nt = 0; nt < 8; nt++) {
                const int cl = warp_n * 64 + nt * 8 + (lane & 3) * 2;
                const size_t off = rowoff + (n0 + cl);
                const uint32_t hb = *(const uint32_t*)(hi_in + off);
                const uint32_t lb = *(const uint32_t*)(lo_in + off);
                const float2 xh = __half22float2(*(const __half2*)&hb);
                const float2 xl = __half22float2(*(const __half2*)&lb);
                uint32_t w0, w1, v0, v1;
                tf2x32(fk1, fk2, 0u, (uint32_t)off, w0, w1);
                tf2x32(fk1, fk2, 0u, (uint32_t)off + 1u, v0, v1);
                float xn0 = (xh.x + xl.x) + 0.01f * acc[mt][nt][h * 2 + 0]
                            + cbias[cl] + S2B * jax_normal(w0 ^ w1);
                float xn1 = (xh.y + xl.y) + 0.01f * acc[mt][nt][h * 2 + 1]
                            + cbias[cl + 1] + S2B * jax_normal(v0 ^ v1);
                __half h0 = __float2half_rn(xn0);
                __half h1 = __float2half_rn(xn1);
                __half l0 = __float2half_rn(xn0 - __half2float(h0));
                __half l1 = __float2half_rn(xn1 - __half2float(h1));
                *(uint32_t*)(hi_out + off) =
                    (uint32_t)__half_as_ushort(h0) |
                    ((uint32_t)__half_as_ushort(h1) << 16);
                *(uint32_t*)(lo_out + off) =
                    (uint32_t)__half_as_ushort(l0) |
                    ((uint32_t)__half_as_ushort(l1) << 16);
                if (fout)
                    *(float2*)(fout + off) = make_float2(xn0, xn1);
            }
        }
    }
}

// ---------------------------------------------------------------------------
// Host side
// ---------------------------------------------------------------------------
typedef CUresult (*PFN_encode)(CUtensorMap*, CUtensorMapDataType, cuuint32_t,
                               void*, const cuuint64_t*, const cuuint64_t*,
                               const cuuint32_t*, const cuuint32_t*,
                               CUtensorMapInterleave, CUtensorMapSwizzle,
                               CUtensorMapL2promotion, CUtensorMapFloatOOBfill);

static void make_map(PFN_encode enc, CUtensorMap* m, void* ptr,
                     uint64_t d0, uint64_t d1) {
    cuuint64_t dims[2] = {d0, d1};
    cuuint64_t strides[1] = {d0 * 2};            // row stride in bytes (fp16)
    cuuint32_t box[2] = {64, 128};               // 64 halves = 128 B inner
    cuuint32_t es[2] = {1, 1};
    enc(m, CU_TENSOR_MAP_DATA_TYPE_FLOAT16, 2, ptr, dims, strides, box, es,
        CU_TENSOR_MAP_INTERLEAVE_NONE, CU_TENSOR_MAP_SWIZZLE_128B,
        CU_TENSOR_MAP_L2_PROMOTION_L2_128B, CU_TENSOR_MAP_FLOAT_OOB_FILL_NONE);
}

extern "C" void kernel_launch(void* const* d_in, const int* in_sizes, int n_in,
                              void* d_out, int out_size) {
    const float* x0 = (const float*)d_in[0];   // (32768, 512)
    const float* W  = (const float*)d_in[1];   // (1024, 512)
    const float* b  = (const float*)d_in[2];   // (512,)
    float* out = (float*)d_out;

    void *hi0, *lo0, *hi1, *lo1, *bhi;
    cudaGetSymbolAddress(&hi0, g_hi0);
    cudaGetSymbolAddress(&lo0, g_lo0);
    cudaGetSymbolAddress(&hi1, g_hi1);
    cudaGetSymbolAddress(&lo1, g_lo1);
    cudaGetSymbolAddress(&bhi, g_Bhi);

    void* fp = nullptr;
    cudaDriverEntryPointQueryResult qr;
    cudaGetDriverEntryPointByVersion("cuTensorMapEncodeTiled", &fp, 12000,
                                     cudaEnableDefault, &qr);
    PFN_encode enc = (PFN_encode)fp;

    CUtensorMap mAhi0, mAlo0, mAhi1, mAlo1, mBhi;
    make_map(enc, &mAhi0, hi0, DIM, BATCH);
    make_map(enc, &mAlo0, lo0, DIM, BATCH);
    make_map(enc, &mAhi1, hi1, DIM, BATCH);
    make_map(enc, &mAlo1, lo1, DIM, BATCH);
    make_map(enc, &mBhi,  bhi, DIM, DIM);

    cudaFuncSetAttribute(step_kernel,
                         cudaFuncAttributeMaxDynamicSharedMemorySize, SMEM_REQ);

    prep_b_kernel<<<(DIM * DIM + 255) / 256, 256>>>(W);
    prep_s_kernel<<<1, DIM>>>(W);
    prep_x_kernel<<<NTOT / 256, 256>>>(x0);

    dim3 grid(DIM / 128, BATCH / 128);   // (4, 256)
    for (int t = 0; t < NUM_STEPS; t++) {
        bool even = (t & 1) == 0;
        const __half* hin = even ? (const __half*)hi0 : (const __half*)hi1;
        const __half* lin = even ? (const __half*)lo0 : (const __half*)lo1;
        __half* hout = even ? (__half*)hi1 : (__half*)hi0;
        __half* lout = even ? (__half*)lo1 : (__half*)lo0;
        float* fo = (t == NUM_STEPS - 1) ? out : nullptr;
        if (even)
            step_kernel<<<grid, 256, SMEM_REQ>>>(mAhi0, mAlo0, mBhi,
                                                 hin, lin, hout, lout, fo, b, t);
        else
            step_kernel<<<grid, 256, SMEM_REQ>>>(mAhi1, mAlo1, mBhi,
                                                 hin, lin, hout, lout, fo, b, t);
    }
}

// round 9
// speedup vs baseline: 4.0744x; 2.4474x over previous
#include <cuda_runtime.h>
#include <cuda.h>
#include <cuda_fp16.h>
#include <cstdint>

// Problem constants
#define BATCH     32768
#define DIM       512
#define NUM_STEPS 100
#define NTOT      (BATCH * DIM)       // 2^24 elements

// ---------------------------------------------------------------------------
// Device scratch (no runtime allocation allowed)
// ---------------------------------------------------------------------------
__device__ __half g_hi0[NTOT];
__device__ __half g_lo0[NTOT];
__device__ __half g_hi1[NTOT];
__device__ __half g_lo1[NTOT];
__device__ float  g_score[NTOT];      // per-step GEMM result (f32)
__device__ __half g_Bhi[DIM * DIM];   // W_top^T [n][k] (fp16)
__device__ float  g_s[DIM];           // s[j] = sum_k W_bot[k][j]

// ---------------------------------------------------------------------------
// PTX helpers (sm_90-baseline: TMA bulk + mbarrier; NO 'a'-gated instrs)
// ---------------------------------------------------------------------------
__device__ __forceinline__ uint32_t smem_u32(const void* p) {
    uint32_t a;
    asm("{ .reg .u64 t; cvta.to.shared.u64 t, %1; cvt.u32.u64 %0, t; }"
        : "=r"(a) : "l"(p));
    return a;
}

#define MBARRIER_INIT(addr, cnt) \
    asm volatile("mbarrier.init.shared.b64 [%0], %1;" \
                 :: "r"((uint32_t)(addr)), "r"((uint32_t)(cnt)) : "memory")

#define MBARRIER_EXPECT_TX(addr, bytes) \
    asm volatile("mbarrier.arrive.expect_tx.shared.b64 _, [%0], %1;" \
                 :: "r"((uint32_t)(addr)), "r"((uint32_t)(bytes)) : "memory")

#define MBARRIER_ARRIVE(addr) \
    asm volatile("mbarrier.arrive.shared.b64 _, [%0];" \
                 :: "r"((uint32_t)(addr)) : "memory")

#define MBARRIER_WAIT_PARITY(addr, parity) do { \
    uint32_t _m = (uint32_t)(addr); \
    uint32_t _p = (uint32_t)(parity); \
    uint32_t _d; \
    asm volatile("{\n\t.reg .pred p;\n\t" \
        "mbarrier.try_wait.parity.acquire.cta.shared::cta.b64 p, [%1], %2;\n\t" \
        "selp.b32 %0, 1, 0, p;\n\t}" : "=r"(_d) : "r"(_m), "r"(_p) : "memory"); \
    if (!_d) { \
        asm volatile("{\n\t.reg .pred P1;\n\t" \
            "WL_%=:\n\t" \
            "mbarrier.try_wait.parity.acquire.cta.shared::cta.b64 P1, [%0], %1, 0x989680;\n\t" \
            "@P1 bra.uni WD_%=;\n\t" \
            "bra.uni WL_%=;\n\t" \
            "WD_%=:\n\t}" :: "r"(_m), "r"(_p) : "memory"); \
    } \
} while (0)

__device__ __forceinline__ void tma_load_2d(uint32_t smem_addr, const void* map,
                                            int cx, int cy, uint32_t mbar) {
    asm volatile(
        "cp.async.bulk.tensor.2d.shared::cta.global.tile.mbarrier::complete_tx::bytes "
        "[%0], [%1, {%2, %3}], [%4];"
        :: "r"(smem_addr), "l"(map), "r"(cx), "r"(cy), "r"(mbar) : "memory");
}

__device__ __forceinline__ void ldsm4(uint32_t* r, uint32_t addr) {
    asm volatile("ldmatrix.sync.aligned.m8n8.x4.shared.b16 {%0,%1,%2,%3}, [%4];"
                 : "=r"(r[0]), "=r"(r[1]), "=r"(r[2]), "=r"(r[3]) : "r"(addr));
}

__device__ __forceinline__ void mma16816(float* d, const uint32_t* a,
                                         const uint32_t* b) {
    asm volatile(
        "mma.sync.aligned.m16n8k16.row.col.f32.f16.f16.f32 "
        "{%0,%1,%2,%3}, {%4,%5,%6,%7}, {%8,%9}, {%0,%1,%2,%3};"
        : "+f"(d[0]), "+f"(d[1]), "+f"(d[2]), "+f"(d[3])
        : "r"(a[0]), "r"(a[1]), "r"(a[2]), "r"(a[3]), "r"(b[0]), "r"(b[1]));
}

// ---------------------------------------------------------------------------
// Threefry-2x32 (20 rounds) + JAX normal — bit-exact (verified round 3/6/7)
// ---------------------------------------------------------------------------
#define TF_ROUND(r) { x0 += x1; x1 = __funnelshift_l(x1, x1, (r)); x1 ^= x0; }

__device__ __forceinline__ void tf2x32(uint32_t k0, uint32_t k1,
                                       uint32_t x0, uint32_t x1,
                                       uint32_t& o0, uint32_t& o1) {
    uint32_t k2 = k0 ^ k1 ^ 0x1BD11BDAu;
    x0 += k0; x1 += k1;
    TF_ROUND(13) TF_ROUND(15) TF_ROUND(26) TF_ROUND(6)
    x0 += k1; x1 += k2 + 1u;
    TF_ROUND(17) TF_ROUND(29) TF_ROUND(16) TF_ROUND(24)
    x0 += k2; x1 += k0 + 2u;
    TF_ROUND(13) TF_ROUND(15) TF_ROUND(26) TF_ROUND(6)
    x0 += k0; x1 += k1 + 3u;
    TF_ROUND(17) TF_ROUND(29) TF_ROUND(16) TF_ROUND(24)
    x0 += k1; x1 += k2 + 4u;
    TF_ROUND(13) TF_ROUND(15) TF_ROUND(26) TF_ROUND(6)
    x0 += k2; x1 += k0 + 5u;
    o0 = x0; o1 = x1;
}

__device__ __forceinline__ float jax_normal(uint32_t bits) {
    float f = __uint_as_float((bits >> 9) | 0x3F800000u) - 1.0f;
    const float lo = __uint_as_float(0xBF7FFFFFu);   // nextafter(-1, 0)
    float u = f * 2.0f + lo;
    float w = -log1pf(-u * u);
    float p;
    if (w < 5.0f) {
        w = w - 2.5f;
        p = 2.81022636e-08f;
        p = fmaf(p, w, 3.43273939e-07f);
        p = fmaf(p, w, -3.5233877e-06f);
        p = fmaf(p, w, -4.39150654e-06f);
        p = fmaf(p, w, 0.00021858087f);
        p = fmaf(p, w, -0.00125372503f);
        p = fmaf(p, w, -0.00417768164f);
        p = fmaf(p, w, 0.246640727f);
        p = fmaf(p, w, 1.50140941f);
    } else {
        w = sqrtf(w) - 3.0f;
        p = -0.000200214257f;
        p = fmaf(p, w, 0.000100950558f);
        p = fmaf(p, w, 0.00134934322f);
        p = fmaf(p, w, -0.00367342844f);
        p = fmaf(p, w, 0.00573950773f);
        p = fmaf(p, w, -0.0076224613f);
        p = fmaf(p, w, 0.00943887047f);
        p = fmaf(p, w, 1.00167406f);
        p = fmaf(p, w, 2.83297682f);
    }
    return 1.41421356237f * (p * u);
}

// ---------------------------------------------------------------------------
// Prep kernels
// ---------------------------------------------------------------------------
__global__ void prep_b_kernel(const float* __restrict__ W) {
    int i = blockIdx.x * blockDim.x + threadIdx.x;   // i = n*512 + k
    if (i < DIM * DIM) {
        int n = i >> 9, k = i & 511;
        g_Bhi[i] = __float2half_rn(W[k * DIM + n]);  // W_top[k][n]
    }
}

__global__ void prep_s_kernel(const float* __restrict__ W) {
    int j = threadIdx.x;   // 512 threads, 1 block
    float s = 0.0f;
    #pragma unroll 8
    for (int k = 0; k < DIM; k++)
        s += W[(DIM + k) * DIM + j];
    g_s[j] = s;
}

__global__ void prep_x_kernel(const float* __restrict__ x0) {
    int i = blockIdx.x * blockDim.x + threadIdx.x;
    float v = x0[i];
    __half h = __float2half_rn(v);
    g_hi0[i] = h;
    g_lo0[i] = __float2half_rn(v - __half2float(h));
}

// ---------------------------------------------------------------------------
// Kernel G: TMA + HMMA GEMM.  score = (x_hi + x_lo) @ W_hi  -> f32 gmem
// CTA tile 128x128, 8 warps (4M x 2N), BK=64, TMA SW128 double buffer.
// ---------------------------------------------------------------------------
#define NCH       8                    // 512 / 64
#define TILE_SZ   16384                // 128 rows x 128 B
#define STAGE_SZ  (3 * TILE_SZ)        // Ahi, Alo, Bhi
#define BAR_OFF   (2 * STAGE_SZ)       // 98304
#define SMEM_REQ  (BAR_OFF + 64 + 1024)   // + align slack

__global__ void __launch_bounds__(256, 2)
step_gemm(const __grid_constant__ CUtensorMap mAhi,
          const __grid_constant__ CUtensorMap mAlo,
          const __grid_constant__ CUtensorMap mBhi,
          float* __restrict__ score) {
    extern __shared__ char smem[];
    const uint32_t sbRaw = smem_u32(smem);
    const uint32_t base  = (sbRaw + 1023u) & ~1023u;

    const uint32_t FULL0 = base + BAR_OFF,      FULL1 = base + BAR_OFF + 8;
    const uint32_t EMPT0 = base + BAR_OFF + 16, EMPT1 = base + BAR_OFF + 24;

    const int tid = threadIdx.x;
    const int wid = tid >> 5, lane = tid & 31;
    const int warp_m = wid & 3, warp_n = wid >> 2;
    const int m0 = blockIdx.y * 128, n0 = blockIdx.x * 128;

    if (tid == 0) {
        MBARRIER_INIT(FULL0, 1);
        MBARRIER_INIT(FULL1, 1);
        MBARRIER_INIT(EMPT0, 256);
        MBARRIER_INIT(EMPT1, 256);
    }
    __syncthreads();

    float acc[2][8][4];
    #pragma unroll
    for (int mt = 0; mt < 2; mt++)
        #pragma unroll
        for (int nt = 0; nt < 8; nt++)
            #pragma unroll
            for (int q = 0; q < 4; q++) acc[mt][nt][q] = 0.0f;

    // Per-thread ldmatrix addressing (SW128: XOR sub-offset with (row&7)*16)
    const uint32_t xorS   = (uint32_t)(lane & 7) << 4;
    const uint32_t aRowOff = (uint32_t)(warp_m * 32 + (lane & 15)) * 128u;
    const uint32_t aSub    = (uint32_t)(lane >> 4) << 4;
    const uint32_t bRowOff = (uint32_t)(warp_n * 64 + (lane & 7) +
                                        ((lane >> 4) << 3)) * 128u;
    const uint32_t bSub    = (uint32_t)((lane >> 3) & 1) << 4;

    const uint32_t stg0 = base, stg1 = base + STAGE_SZ;

    if (tid == 0) {
        MBARRIER_EXPECT_TX(FULL0, STAGE_SZ);
        tma_load_2d(stg0,               &mAhi, 0, m0, FULL0);
        tma_load_2d(stg0 + TILE_SZ,     &mAlo, 0, m0, FULL0);
        tma_load_2d(stg0 + 2 * TILE_SZ, &mBhi, 0, n0, FULL0);
    }

    #pragma unroll 1
    for (int c = 0; c < NCH; c++) {
        const int sbi = c & 1;
        const uint32_t sb = sbi ? stg1 : stg0;
        MBARRIER_WAIT_PARITY(sbi ? FULL1 : FULL0, (c >> 1) & 1);

        if (tid == 0 && c + 1 < NCH) {
            const int s2 = (c + 1) & 1, k2 = (c + 1) >> 1;
            const uint32_t sn = s2 ? stg1 : stg0;
            if (k2 > 0) MBARRIER_WAIT_PARITY(s2 ? EMPT1 : EMPT0, (k2 - 1) & 1);
            MBARRIER_EXPECT_TX(s2 ? FULL1 : FULL0, STAGE_SZ);
            const int k0 = (c + 1) * 64;
            tma_load_2d(sn,               &mAhi, k0, m0, s2 ? FULL1 : FULL0);
            tma_load_2d(sn + TILE_SZ,     &mAlo, k0, m0, s2 ? FULL1 : FULL0);
            tma_load_2d(sn + 2 * TILE_SZ, &mBhi, k0, n0, s2 ? FULL1 : FULL0);
        }

        #pragma unroll
        for (int s = 0; s < 4; s++) {
            const uint32_t ka = ((uint32_t)(s * 32) + aSub) ^ xorS;
            const uint32_t kb = ((uint32_t)(s * 32) + bSub) ^ xorS;
            uint32_t ahi[2][4], alo[2][4];
            #pragma unroll
            for (int mt = 0; mt < 2; mt++) {
                const uint32_t ao = sb + aRowOff + (uint32_t)(mt * 16 * 128) + ka;
                ldsm4(ahi[mt], ao);
                ldsm4(alo[mt], ao + TILE_SZ);
            }
            #pragma unroll
            for (int p = 0; p < 4; p++) {
                uint32_t bh[4];
                ldsm4(bh, sb + 2 * TILE_SZ + bRowOff +
                          (uint32_t)(p * 16 * 128) + kb);
                #pragma unroll
                for (int mt = 0; mt < 2; mt++) {
                    mma16816(acc[mt][2 * p],     ahi[mt], bh);
                    mma16816(acc[mt][2 * p],     alo[mt], bh);
                    mma16816(acc[mt][2 * p + 1], ahi[mt], bh + 2);
                    mma16816(acc[mt][2 * p + 1], alo[mt], bh + 2);
                }
            }
        }
        MBARRIER_ARRIVE(sbi ? EMPT1 : EMPT0);
    }

    // Store raw score (f32) — epilogue kernel consumes it
    #pragma unroll
    for (int mt = 0; mt < 2; mt++)
        #pragma unroll
        for (int h = 0; h < 2; h++) {
            const int r = m0 + warp_m * 32 + mt * 16 + (lane >> 2) + h * 8;
            const size_t rowoff = (size_t)r * DIM;
            #pragma unroll
            for (int nt = 0; nt < 8; nt++) {
                const int cl = warp_n * 64 + nt * 8 + (lane & 3) * 2;
                *(float2*)(score + rowoff + (n0 + cl)) =
                    make_float2(acc[mt][nt][h * 2], acc[mt][nt][h * 2 + 1]);
            }
        }
}

// ---------------------------------------------------------------------------
// Kernel E: streaming epilogue.  x_next = (hi+lo) + 0.01*score + cbias + s*n
// 256 threads x 8 elems; high occupancy; 8 independent threefry chains.
// ---------------------------------------------------------------------------
__global__ void __launch_bounds__(256, 4)
step_epi(const __half* __restrict__ hi_in,
         const __half* __restrict__ lo_in,
         const float* __restrict__ score,
         __half* __restrict__ hi_out,
         __half* __restrict__ lo_out,
         float* __restrict__ fout,       // non-null only on last step
         const float* __restrict__ bias,
         int t) {
    __shared__ float cbias[DIM];
    __shared__ uint32_t fk[2];

    const int tid = threadIdx.x;
    const float tf = (float)t;
    for (int c = tid; c < DIM; c += 256)
        cbias[c] = 0.01f * (tf * g_s[c] + bias[c]);
    if (tid == 0) {
        uint32_t a, b2;
        tf2x32(0u, 42u, 0u, (uint32_t)t, a, b2);
        fk[0] = a; fk[1] = b2;
    }
    __syncthreads();

    const uint32_t fk1 = fk[0], fk2 = fk[1];
    const float S2B = sqrtf(2.0f * 0.01f);

    const size_t base = (size_t)blockIdx.x * 2048 + (size_t)tid * 8;
    const int c0 = (int)(base & 511u);

    const float4 s0 = *(const float4*)(score + base);
    const float4 s1 = *(const float4*)(score + base + 4);
    const uint4 hb = *(const uint4*)(hi_in + base);
    const uint4 lb = *(const uint4*)(lo_in + base);

    float xo[8];
    {
        const uint32_t* hp = &hb.x;
        const uint32_t* lp = &lb.x;
        #pragma unroll
        for (int q = 0; q < 4; q++) {
            float2 h2 = __half22float2(*(const __half2*)&hp[q]);
            float2 l2 = __half22float2(*(const __half2*)&lp[q]);
            xo[2 * q]     = h2.x + l2.x;
            xo[2 * q + 1] = h2.y + l2.y;
        }
    }

    float xn[8];
    const float* sp0 = &s0.x;
    const float* sp1 = &s1.x;
    #pragma unroll
    for (int e = 0; e < 8; e++) {
        uint32_t w0, w1;
        tf2x32(fk1, fk2, 0u, (uint32_t)base + (uint32_t)e, w0, w1);
        float sc = (e < 4) ? sp0[e] : sp1[e - 4];
        xn[e] = xo[e] + 0.01f * sc + cbias[c0 + e] + S2B * jax_normal(w0 ^ w1);
    }

    uint4 ho, lo;
    uint32_t* hop = &ho.x;
    uint32_t* lop = &lo.x;
    #pragma unroll
    for (int q = 0; q < 4; q++) {
        __half h0 = __float2half_rn(xn[2 * q]);
        __half h1 = __float2half_rn(xn[2 * q + 1]);
        __half l0 = __float2half_rn(xn[2 * q]     - __half2float(h0));
        __half l1 = __float2half_rn(xn[2 * q + 1] - __half2float(h1));
        hop[q] = (uint32_t)__half_as_ushort(h0) |
                 ((uint32_t)__half_as_ushort(h1) << 16);
        lop[q] = (uint32_t)__half_as_ushort(l0) |
                 ((uint32_t)__half_as_ushort(l1) << 16);
    }
    *(uint4*)(hi_out + base) = ho;
    *(uint4*)(lo_out + base) = lo;
    if (fout) {
        *(float4*)(fout + base)     = make_float4(xn[0], xn[1], xn[2], xn[3]);
        *(float4*)(fout + base + 4) = make_float4(xn[4], xn[5], xn[6], xn[7]);
    }
}

// ---------------------------------------------------------------------------
// Host side
// ---------------------------------------------------------------------------
typedef CUresult (*PFN_encode)(CUtensorMap*, CUtensorMapDataType, cuuint32_t,
                               void*, const cuuint64_t*, const cuuint64_t*,
                               const cuuint32_t*, const cuuint32_t*,
                               CUtensorMapInterleave, CUtensorMapSwizzle,
                               CUtensorMapL2promotion, CUtensorMapFloatOOBfill);

static void make_map(PFN_encode enc, CUtensorMap* m, void* ptr,
                     uint64_t d0, uint64_t d1) {
    cuuint64_t dims[2] = {d0, d1};
    cuuint64_t strides[1] = {d0 * 2};            // row stride in bytes (fp16)
    cuuint32_t box[2] = {64, 128};               // 64 halves = 128 B inner
    cuuint32_t es[2] = {1, 1};
    enc(m, CU_TENSOR_MAP_DATA_TYPE_FLOAT16, 2, ptr, dims, strides, box, es,
        CU_TENSOR_MAP_INTERLEAVE_NONE, CU_TENSOR_MAP_SWIZZLE_128B,
        CU_TENSOR_MAP_L2_PROMOTION_L2_128B, CU_TENSOR_MAP_FLOAT_OOB_FILL_NONE);
}

extern "C" void kernel_launch(void* const* d_in, const int* in_sizes, int n_in,
                              void* d_out, int out_size) {
    const float* x0 = (const float*)d_in[0];   // (32768, 512)
    const float* W  = (const float*)d_in[1];   // (1024, 512)
    const float* b  = (const float*)d_in[2];   // (512,)
    float* out = (float*)d_out;

    void *hi0, *lo0, *hi1, *lo1, *bhi, *scr;
    cudaGetSymbolAddress(&hi0, g_hi0);
    cudaGetSymbolAddress(&lo0, g_lo0);
    cudaGetSymbolAddress(&hi1, g_hi1);
    cudaGetSymbolAddress(&lo1, g_lo1);
    cudaGetSymbolAddress(&bhi, g_Bhi);
    cudaGetSymbolAddress(&scr, g_score);

    void* fp = nullptr;
    cudaDriverEntryPointQueryResult qr;
    cudaGetDriverEntryPointByVersion("cuTensorMapEncodeTiled", &fp, 12000,
                                     cudaEnableDefault, &qr);
    PFN_encode enc = (PFN_encode)fp;

    CUtensorMap mAhi0, mAlo0, mAhi1, mAlo1, mBhi;
    make_map(enc, &mAhi0, hi0, DIM, BATCH);
    make_map(enc, &mAlo0, lo0, DIM, BATCH);
    make_map(enc, &mAhi1, hi1, DIM, BATCH);
    make_map(enc, &mAlo1, lo1, DIM, BATCH);
    make_map(enc, &mBhi,  bhi, DIM, DIM);

    cudaFuncSetAttribute(step_gemm,
                         cudaFuncAttributeMaxDynamicSharedMemorySize, SMEM_REQ);

    prep_b_kernel<<<(DIM * DIM + 255) / 256, 256>>>(W);
    prep_s_kernel<<<1, DIM>>>(W);
    prep_x_kernel<<<NTOT / 256, 256>>>(x0);

    dim3 gridG(DIM / 128, BATCH / 128);   // (4, 256)
    const int gridE = NTOT / 2048;        // 8192
    float* score = (float*)scr;

    for (int t = 0; t < NUM_STEPS; t++) {
        bool even = (t & 1) == 0;
        const __half* hin = even ? (const __half*)hi0 : (const __half*)hi1;
        const __half* lin = even ? (const __half*)lo0 : (const __half*)lo1;
        __half* hout = even ? (__half*)hi1 : (__half*)hi0;
        __half* lout = even ? (__half*)lo1 : (__half*)lo0;
        float* fo = (t == NUM_STEPS - 1) ? out : nullptr;
        if (even)
            step_gemm<<<gridG, 256, SMEM_REQ>>>(mAhi0, mAlo0, mBhi, score);
        else
            step_gemm<<<gridG, 256, SMEM_REQ>>>(mAhi1, mAlo1, mBhi, score);
        step_epi<<<gridE, 256>>>(hin, lin, score, hout, lout, fo, b, t);
    }
}

// round 11
// speedup vs baseline: 5.3993x; 1.3252x over previous
#include <cuda_runtime.h>
#include <cuda.h>
#include <cuda_fp16.h>
#include <cstdint>

// Problem constants
#define BATCH     32768
#define DIM       512
#define NUM_STEPS 100
#define NTOT      (BATCH * DIM)       // 2^24 elements

// ---------------------------------------------------------------------------
// Device scratch (no runtime allocation allowed)
// ---------------------------------------------------------------------------
__device__ __half g_hi0[NTOT];
__device__ __half g_lo0[NTOT];
__device__ __half g_hi1[NTOT];
__device__ __half g_lo1[NTOT];
__device__ float  g_score[NTOT];      // per-step GEMM result (f32)
__device__ __half g_Bhi[DIM * DIM];   // W_top^T [n][k] (fp16)
__device__ float  g_s[DIM];           // s[j] = sum_k W_bot[k][j]

// ---------------------------------------------------------------------------
// PTX helpers (sm_90-baseline: TMA bulk + mbarrier; NO 'a'-gated instrs)
// ---------------------------------------------------------------------------
__device__ __forceinline__ uint32_t smem_u32(const void* p) {
    uint32_t a;
    asm("{ .reg .u64 t; cvta.to.shared.u64 t, %1; cvt.u32.u64 %0, t; }"
        : "=r"(a) : "l"(p));
    return a;
}

#define MBARRIER_INIT(addr, cnt) \
    asm volatile("mbarrier.init.shared.b64 [%0], %1;" \
                 :: "r"((uint32_t)(addr)), "r"((uint32_t)(cnt)) : "memory")

#define MBARRIER_EXPECT_TX(addr, bytes) \
    asm volatile("mbarrier.arrive.expect_tx.shared.b64 _, [%0], %1;" \
                 :: "r"((uint32_t)(addr)), "r"((uint32_t)(bytes)) : "memory")

#define MBARRIER_ARRIVE(addr) \
    asm volatile("mbarrier.arrive.shared.b64 _, [%0];" \
                 :: "r"((uint32_t)(addr)) : "memory")

#define MBARRIER_WAIT_PARITY(addr, parity) do { \
    uint32_t _m = (uint32_t)(addr); \
    uint32_t _p = (uint32_t)(parity); \
    uint32_t _d; \
    asm volatile("{\n\t.reg .pred p;\n\t" \
        "mbarrier.try_wait.parity.acquire.cta.shared::cta.b64 p, [%1], %2;\n\t" \
        "selp.b32 %0, 1, 0, p;\n\t}" : "=r"(_d) : "r"(_m), "r"(_p) : "memory"); \
    if (!_d) { \
        asm volatile("{\n\t.reg .pred P1;\n\t" \
            "WL_%=:\n\t" \
            "mbarrier.try_wait.parity.acquire.cta.shared::cta.b64 P1, [%0], %1, 0x989680;\n\t" \
            "@P1 bra.uni WD_%=;\n\t" \
            "bra.uni WL_%=;\n\t" \
            "WD_%=:\n\t}" :: "r"(_m), "r"(_p) : "memory"); \
    } \
} while (0)

__device__ __forceinline__ void tma_load_2d(uint32_t smem_addr, const void* map,
                                            int cx, int cy, uint32_t mbar) {
    asm volatile(
        "cp.async.bulk.tensor.2d.shared::cta.global.tile.mbarrier::complete_tx::bytes "
        "[%0], [%1, {%2, %3}], [%4];"
        :: "r"(smem_addr), "l"(map), "r"(cx), "r"(cy), "r"(mbar) : "memory");
}

__device__ __forceinline__ void ldsm4(uint32_t* r, uint32_t addr) {
    asm volatile("ldmatrix.sync.aligned.m8n8.x4.shared.b16 {%0,%1,%2,%3}, [%4];"
                 : "=r"(r[0]), "=r"(r[1]), "=r"(r[2]), "=r"(r[3]) : "r"(addr));
}

__device__ __forceinline__ void mma16816(float* d, const uint32_t* a,
                                         const uint32_t* b) {
    asm volatile(
        "mma.sync.aligned.m16n8k16.row.col.f32.f16.f16.f32 "
        "{%0,%1,%2,%3}, {%4,%5,%6,%7}, {%8,%9}, {%0,%1,%2,%3};"
        : "+f"(d[0]), "+f"(d[1]), "+f"(d[2]), "+f"(d[3])
        : "r"(a[0]), "r"(a[1]), "r"(a[2]), "r"(a[3]), "r"(b[0]), "r"(b[1]));
}

// ---------------------------------------------------------------------------
// Threefry-2x32 (20 rounds) + JAX normal — verified rounds 3/6/7/9
// ---------------------------------------------------------------------------
#define TF_ROUND(r) { x0 += x1; x1 = __funnelshift_l(x1, x1, (r)); x1 ^= x0; }

__device__ __forceinline__ void tf2x32(uint32_t k0, uint32_t k1,
                                       uint32_t x0, uint32_t x1,
                                       uint32_t& o0, uint32_t& o1) {
    uint32_t k2 = k0 ^ k1 ^ 0x1BD11BDAu;
    x0 += k0; x1 += k1;
    TF_ROUND(13) TF_ROUND(15) TF_ROUND(26) TF_ROUND(6)
    x0 += k1; x1 += k2 + 1u;
    TF_ROUND(17) TF_ROUND(29) TF_ROUND(16) TF_ROUND(24)
    x0 += k2; x1 += k0 + 2u;
    TF_ROUND(13) TF_ROUND(15) TF_ROUND(26) TF_ROUND(6)
    x0 += k0; x1 += k1 + 3u;
    TF_ROUND(17) TF_ROUND(29) TF_ROUND(16) TF_ROUND(24)
    x0 += k1; x1 += k2 + 4u;
    TF_ROUND(13) TF_ROUND(15) TF_ROUND(26) TF_ROUND(6)
    x0 += k2; x1 += k0 + 5u;
    o0 = x0; o1 = x1;
}

// Fast log variant: __logf (MUFU.LG2) instead of log1pf. Noise perturbation
// ~1e-6 abs -> ~1e-7 in final output (noise carries ~6% of output norm).
__device__ __forceinline__ float jax_normal(uint32_t bits) {
    float f = __uint_as_float((bits >> 9) | 0x3F800000u) - 1.0f;
    const float lo = __uint_as_float(0xBF7FFFFFu);   // nextafter(-1, 0)
    float u = f * 2.0f + lo;
    float w = -__logf(fmaf(-u, u, 1.0f));
    float p;
    if (w < 5.0f) {
        w = w - 2.5f;
        p = 2.81022636e-08f;
        p = fmaf(p, w, 3.43273939e-07f);
        p = fmaf(p, w, -3.5233877e-06f);
        p = fmaf(p, w, -4.39150654e-06f);
        p = fmaf(p, w, 0.00021858087f);
        p = fmaf(p, w, -0.00125372503f);
        p = fmaf(p, w, -0.00417768164f);
        p = fmaf(p, w, 0.246640727f);
        p = fmaf(p, w, 1.50140941f);
    } else {
        w = sqrtf(w) - 3.0f;
        p = -0.000200214257f;
        p = fmaf(p, w, 0.000100950558f);
        p = fmaf(p, w, 0.00134934322f);
        p = fmaf(p, w, -0.00367342844f);
        p = fmaf(p, w, 0.00573950773f);
        p = fmaf(p, w, -0.0076224613f);
        p = fmaf(p, w, 0.00943887047f);
        p = fmaf(p, w, 1.00167406f);
        p = fmaf(p, w, 2.83297682f);
    }
    return 1.41421356237f * (p * u);
}

// ---------------------------------------------------------------------------
// Prep kernels
// ---------------------------------------------------------------------------
__global__ void prep_b_kernel(const float* __restrict__ W) {
    int i = blockIdx.x * blockDim.x + threadIdx.x;   // i = n*512 + k
    if (i < DIM * DIM) {
        int n = i >> 9, k = i & 511;
        g_Bhi[i] = __float2half_rn(W[k * DIM + n]);  // W_top[k][n]
    }
}

__global__ void prep_s_kernel(const float* __restrict__ W) {
    int j = threadIdx.x;   // 512 threads, 1 block
    float s = 0.0f;
    #pragma unroll 8
    for (int k = 0; k < DIM; k++)
        s += W[(DIM + k) * DIM + j];
    g_s[j] = s;
}

__global__ void prep_x_kernel(const float* __restrict__ x0) {
    int i = blockIdx.x * blockDim.x + threadIdx.x;
    float v = x0[i];
    __half h = __float2half_rn(v);
    g_hi0[i] = h;
    g_lo0[i] = __float2half_rn(v - __half2float(h));
}

// ---------------------------------------------------------------------------
// Kernel G: TMA + HMMA GEMM.  score = x_hi @ W_hi  -> f32 gmem
// (x carried as hi+lo; only the MMA input is fp16-quantized.)
// CTA tile 128x128, 8 warps (4M x 2N), BK=64, TMA SW128 double buffer.
// ---------------------------------------------------------------------------
#define NCH       8                    // 512 / 64
#define TILE_SZ   16384                // 128 rows x 128 B
#define STAGE_SZ  (2 * TILE_SZ)        // Ahi, Bhi
#define BAR_OFF   (2 * STAGE_SZ)       // 65536
#define SMEM_REQ  (BAR_OFF + 64 + 1024)   // + align slack

__global__ void __launch_bounds__(256, 2)
step_gemm(const __grid_constant__ CUtensorMap mAhi,
          const __grid_constant__ CUtensorMap mBhi,
          float* __restrict__ score) {
    extern __shared__ char smem[];
    const uint32_t sbRaw = smem_u32(smem);
    const uint32_t base  = (sbRaw + 1023u) & ~1023u;

    const uint32_t FULL0 = base + BAR_OFF,      FULL1 = base + BAR_OFF + 8;
    const uint32_t EMPT0 = base + BAR_OFF + 16, EMPT1 = base + BAR_OFF + 24;

    const int tid = threadIdx.x;
    const int wid = tid >> 5, lane = tid & 31;
    const int warp_m = wid & 3, warp_n = wid >> 2;
    const int m0 = blockIdx.y * 128, n0 = blockIdx.x * 128;

    if (tid == 0) {
        MBARRIER_INIT(FULL0, 1);
        MBARRIER_INIT(FULL1, 1);
        MBARRIER_INIT(EMPT0, 256);
        MBARRIER_INIT(EMPT1, 256);
    }
    __syncthreads();

    float acc[2][8][4];
    #pragma unroll
    for (int mt = 0; mt < 2; mt++)
        #pragma unroll
        for (int nt = 0; nt < 8; nt++)
            #pragma unroll
            for (int q = 0; q < 4; q++) acc[mt][nt][q] = 0.0f;

    // Per-thread ldmatrix addressing (SW128: XOR sub-offset with (row&7)*16)
    const uint32_t xorS   = (uint32_t)(lane & 7) << 4;
    const uint32_t aRowOff = (uint32_t)(warp_m * 32 + (lane & 15)) * 128u;
    const uint32_t aSub    = (uint32_t)(lane >> 4) << 4;
    const uint32_t bRowOff = (uint32_t)(warp_n * 64 + (lane & 7) +
                                        ((lane >> 4) << 3)) * 128u;
    const uint32_t bSub    = (uint32_t)((lane >> 3) & 1) << 4;

    const uint32_t stg0 = base, stg1 = base + STAGE_SZ;

    if (tid == 0) {
        MBARRIER_EXPECT_TX(FULL0, STAGE_SZ);
        tma_load_2d(stg0,           &mAhi, 0, m0, FULL0);
        tma_load_2d(stg0 + TILE_SZ, &mBhi, 0, n0, FULL0);
    }

    #pragma unroll 1
    for (int c = 0; c < NCH; c++) {
        const int sbi = c & 1;
        const uint32_t sb = sbi ? stg1 : stg0;
        MBARRIER_WAIT_PARITY(sbi ? FULL1 : FULL0, (c >> 1) & 1);

        if (tid == 0 && c + 1 < NCH) {
            const int s2 = (c + 1) & 1, k2 = (c + 1) >> 1;
            const uint32_t sn = s2 ? stg1 : stg0;
            if (k2 > 0) MBARRIER_WAIT_PARITY(s2 ? EMPT1 : EMPT0, (k2 - 1) & 1);
            MBARRIER_EXPECT_TX(s2 ? FULL1 : FULL0, STAGE_SZ);
            const int k0 = (c + 1) * 64;
            tma_load_2d(sn,           &mAhi, k0, m0, s2 ? FULL1 : FULL0);
            tma_load_2d(sn + TILE_SZ, &mBhi, k0, n0, s2 ? FULL1 : FULL0);
        }

        #pragma unroll
        for (int s = 0; s < 4; s++) {
            const uint32_t ka = ((uint32_t)(s * 32) + aSub) ^ xorS;
            const uint32_t kb = ((uint32_t)(s * 32) + bSub) ^ xorS;
            uint32_t ahi[2][4];
            #pragma unroll
            for (int mt = 0; mt < 2; mt++)
                ldsm4(ahi[mt], sb + aRowOff + (uint32_t)(mt * 16 * 128) + ka);
            #pragma unroll
            for (int p = 0; p < 4; p++) {
                uint32_t bh[4];
                ldsm4(bh, sb + TILE_SZ + bRowOff +
                          (uint32_t)(p * 16 * 128) + kb);
                #pragma unroll
                for (int mt = 0; mt < 2; mt++) {
                    mma16816(acc[mt][2 * p],     ahi[mt], bh);
                    mma16816(acc[mt][2 * p + 1], ahi[mt], bh + 2);
                }
            }
        }
        MBARRIER_ARRIVE(sbi ? EMPT1 : EMPT0);
    }

    // Store raw score (f32) — epilogue kernel consumes it
    #pragma unroll
    for (int mt = 0; mt < 2; mt++)
        #pragma unroll
        for (int h = 0; h < 2; h++) {
            const int r = m0 + warp_m * 32 + mt * 16 + (lane >> 2) + h * 8;
            const size_t rowoff = (size_t)r * DIM;
            #pragma unroll
            for (int nt = 0; nt < 8; nt++) {
                const int cl = warp_n * 64 + nt * 8 + (lane & 3) * 2;
                *(float2*)(score + rowoff + (n0 + cl)) =
                    make_float2(acc[mt][nt][h * 2], acc[mt][nt][h * 2 + 1]);
            }
        }
}

// ---------------------------------------------------------------------------
// Kernel E: streaming epilogue.  x_next = (hi+lo) + 0.01*score + cbias + s*n
// 256 threads x 8 elems; high occupancy; 8 independent threefry chains.
// ---------------------------------------------------------------------------
__global__ void __launch_bounds__(256, 4)
step_epi(const __half* __restrict__ hi_in,
         const __half* __restrict__ lo_in,
         const float* __restrict__ score,
         __half* __restrict__ hi_out,
         __half* __restrict__ lo_out,
         float* __restrict__ fout,       // non-null only on last step
         const float* __restrict__ bias,
         int t) {
    __shared__ float cbias[DIM];
    __shared__ uint32_t fk[2];

    const int tid = threadIdx.x;
    const float tf = (float)t;
    for (int c = tid; c < DIM; c += 256)
        cbias[c] = 0.01f * (tf * g_s[c] + bias[c]);
    if (tid == 0) {
        uint32_t a, b2;
        tf2x32(0u, 42u, 0u, (uint32_t)t, a, b2);
        fk[0] = a; fk[1] = b2;
    }
    __syncthreads();

    const uint32_t fk1 = fk[0], fk2 = fk[1];
    const float S2B = sqrtf(2.0f * 0.01f);

    const size_t base = (size_t)blockIdx.x * 2048 + (size_t)tid * 8;
    const int c0 = (int)(base & 511u);

    const float4 s0 = *(const float4*)(score + base);
    const float4 s1 = *(const float4*)(score + base + 4);
    const uint4 hb = *(const uint4*)(hi_in + base);
    const uint4 lb = *(const uint4*)(lo_in + base);

    float xo[8];
    {
        const uint32_t* hp = &hb.x;
        const uint32_t* lp = &lb.x;
        #pragma unroll
        for (int q = 0; q < 4; q++) {
            float2 h2 = __half22float2(*(const __half2*)&hp[q]);
            float2 l2 = __half22float2(*(const __half2*)&lp[q]);
            xo[2 * q]     = h2.x + l2.x;
            xo[2 * q + 1] = h2.y + l2.y;
        }
    }

    float xn[8];
    const float* sp0 = &s0.x;
    const float* sp1 = &s1.x;
    #pragma unroll
    for (int e = 0; e < 8; e++) {
        uint32_t w0, w1;
        tf2x32(fk1, fk2, 0u, (uint32_t)base + (uint32_t)e, w0, w1);
        float sc = (e < 4) ? sp0[e] : sp1[e - 4];
        xn[e] = xo[e] + 0.01f * sc + cbias[c0 + e] + S2B * jax_normal(w0 ^ w1);
    }

    uint4 ho, lo;
    uint32_t* hop = &ho.x;
    uint32_t* lop = &lo.x;
    #pragma unroll
    for (int q = 0; q < 4; q++) {
        __half2 hh = __floats2half2_rn(xn[2 * q], xn[2 * q + 1]);
        float r0 = xn[2 * q]     - __low2float(hh);
        float r1 = xn[2 * q + 1] - __high2float(hh);
        __half2 ll = __floats2half2_rn(r0, r1);
        hop[q] = *(uint32_t*)&hh;
        lop[q] = *(uint32_t*)&ll;
    }
    *(uint4*)(hi_out + base) = ho;
    *(uint4*)(lo_out + base) = lo;
    if (fout) {
        *(float4*)(fout + base)     = make_float4(xn[0], xn[1], xn[2], xn[3]);
        *(float4*)(fout + base + 4) = make_float4(xn[4], xn[5], xn[6], xn[7]);
    }
}

// ---------------------------------------------------------------------------
// Host side
// ---------------------------------------------------------------------------
typedef CUresult (*PFN_encode)(CUtensorMap*, CUtensorMapDataType, cuuint32_t,
                               void*, const cuuint64_t*, const cuuint64_t*,
                               const cuuint32_t*, const cuuint32_t*,
                               CUtensorMapInterleave, CUtensorMapSwizzle,
                               CUtensorMapL2promotion, CUtensorMapFloatOOBfill);

static void make_map(PFN_encode enc, CUtensorMap* m, void* ptr,
                     uint64_t d0, uint64_t d1) {
    cuuint64_t dims[2] = {d0, d1};
    cuuint64_t strides[1] = {d0 * 2};            // row stride in bytes (fp16)
    cuuint32_t box[2] = {64, 128};               // 64 halves = 128 B inner
    cuuint32_t es[2] = {1, 1};
    enc(m, CU_TENSOR_MAP_DATA_TYPE_FLOAT16, 2, ptr, dims, strides, box, es,
        CU_TENSOR_MAP_INTERLEAVE_NONE, CU_TENSOR_MAP_SWIZZLE_128B,
        CU_TENSOR_MAP_L2_PROMOTION_L2_128B, CU_TENSOR_MAP_FLOAT_OOB_FILL_NONE);
}

extern "C" void kernel_launch(void* const* d_in, const int* in_sizes, int n_in,
                              void* d_out, int out_size) {
    const float* x0 = (const float*)d_in[0];   // (32768, 512)
    const float* W  = (const float*)d_in[1];   // (1024, 512)
    const float* b  = (const float*)d_in[2];   // (512,)
    float* out = (float*)d_out;

    void *hi0, *lo0, *hi1, *lo1, *bhi, *scr;
    cudaGetSymbolAddress(&hi0, g_hi0);
    cudaGetSymbolAddress(&lo0, g_lo0);
    cudaGetSymbolAddress(&hi1, g_hi1);
    cudaGetSymbolAddress(&lo1, g_lo1);
    cudaGetSymbolAddress(&bhi, g_Bhi);
    cudaGetSymbolAddress(&scr, g_score);

    void* fp = nullptr;
    cudaDriverEntryPointQueryResult qr;
    cudaGetDriverEntryPointByVersion("cuTensorMapEncodeTiled", &fp, 12000,
                                     cudaEnableDefault, &qr);
    PFN_encode enc = (PFN_encode)fp;

    CUtensorMap mAhi0, mAhi1, mBhi;
    make_map(enc, &mAhi0, hi0, DIM, BATCH);
    make_map(enc, &mAhi1, hi1, DIM, BATCH);
    make_map(enc, &mBhi,  bhi, DIM, DIM);

    cudaFuncSetAttribute(step_gemm,
                         cudaFuncAttributeMaxDynamicSharedMemorySize, SMEM_REQ);

    prep_b_kernel<<<(DIM * DIM + 255) / 256, 256>>>(W);
    prep_s_kernel<<<1, DIM>>>(W);
    prep_x_kernel<<<NTOT / 256, 256>>>(x0);

    dim3 gridG(DIM / 128, BATCH / 128);   // (4, 256)
    const int gridE = NTOT / 2048;        // 8192
    float* score = (float*)scr;

    for (int t = 0; t < NUM_STEPS; t++) {
        bool even = (t & 1) == 0;
        const __half* hin = even ? (const __half*)hi0 : (const __half*)hi1;
        const __half* lin = even ? (const __half*)lo0 : (const __half*)lo1;
        __half* hout = even ? (__half*)hi1 : (__half*)hi0;
        __half* lout = even ? (__half*)lo1 : (__half*)lo0;
        float* fo = (t == NUM_STEPS - 1) ? out : nullptr;
        if (even)
            step_gemm<<<gridG, 256, SMEM_REQ>>>(mAhi0, mBhi, score);
        else
            step_gemm<<<gridG, 256, SMEM_REQ>>>(mAhi1, mBhi, score);
        step_epi<<<gridE, 256>>>(hin, lin, score, hout, lout, fo, b, t);
    }
}